// round 13
// baseline (speedup 1.0000x reference)
#include <cuda_runtime.h>
#include <cuda_fp16.h>
#include <cuda_bf16.h>
#include <cstdint>

#define VDIM 128
#define NUM_EMB (VDIM * VDIM * VDIM)
#define NCH 20
#define TOTAL_F ((long long)NUM_EMB * NCH)   // 41,943,040
#define TPB 320   // 64 points per block, 5 threads per point

// fp16 copy of the grid: 84 MB — fits the 126 MB L2; kept CLEAN by the
// compare-and-skip convert, re-warmed sequentially before the main pass.
__device__ __half d_gridH[NUM_EMB * NCH];
__device__ float  d_sink;

// Streaming output store (use-once data).
__device__ __forceinline__ void stg_out(float4* p, float4 v) {
    asm volatile("st.global.cs.v4.f32 [%0], {%1,%2,%3,%4};"
                 :: "l"(p), "f"(v.x), "f"(v.y), "f"(v.z), "f"(v.w)
                 : "memory");
}

// fp32 -> fp16 conversion, 8 elems/thread; stores predicated on inequality so
// the table stays clean (no per-replay writeback). Deterministic.
__global__ __launch_bounds__(256) void convert_kernel(const float* __restrict__ g) {
    long long i = ((long long)blockIdx.x * blockDim.x + threadIdx.x) * 8;
    if (i >= TOTAL_F) return;
    const float4* s = (const float4*)(g + i);
    float4 a = __ldcs(s);
    float4 b = __ldcs(s + 1);
    __half2 h0 = __floats2half2_rn(a.x, a.y);
    __half2 h1 = __floats2half2_rn(a.z, a.w);
    __half2 h2 = __floats2half2_rn(b.x, b.y);
    __half2 h3 = __floats2half2_rn(b.z, b.w);
    uint4 v;
    v.x = *(unsigned*)&h0; v.y = *(unsigned*)&h1;
    v.z = *(unsigned*)&h2; v.w = *(unsigned*)&h3;

    uint4* dst = (uint4*)(d_gridH + i);
    uint4 old = *dst;                        // L2-resident in steady state
    if (old.x != v.x || old.y != v.y || old.z != v.z || old.w != v.w)
        *dst = v;
}

// Sequentially touch the whole fp16 table so evicted lines are re-fetched at
// streaming (exactly-once) efficiency instead of random-gather churn in main.
__global__ __launch_bounds__(256) void warm_kernel() {
    const uint4* t4 = (const uint4*)d_gridH;
    long long total = TOTAL_F / 8;           // uint4 = 8 halves
    long long stride = (long long)gridDim.x * blockDim.x;
    unsigned acc = 0;
    for (long long i = (long long)blockIdx.x * blockDim.x + threadIdx.x;
         i < total; i += stride) {
        uint4 v = __ldg(t4 + i);
        acc ^= v.x ^ v.y ^ v.z ^ v.w;
    }
    // impossible-in-practice sink; keeps the loads alive, never actually stores
    if (acc == 0xDEADBEEFu && threadIdx.x == 33) d_sink = (float)acc;
}

__device__ __forceinline__ void acc4(float4& r, float w, unsigned long long q) {
    __half2 lo = *(__half2*)&q;
    __half2 hi = *((__half2*)&q + 1);
    float2 f01 = __half22float2(lo);
    float2 f23 = __half22float2(hi);
    r.x = fmaf(w, f01.x, r.x);
    r.y = fmaf(w, f01.y, r.y);
    r.z = fmaf(w, f23.x, r.z);
    r.w = fmaf(w, f23.y, r.w);
}

__global__ __launch_bounds__(TPB) void dense_grid_interp_kernel(
    const float* __restrict__ x,     // [n, 3]
    float* __restrict__ out,         // [n, 20]
    int n)
{
    int t = blockIdx.x * TPB + threadIdx.x;
    int p = t / 5;        // point index
    int c = t - p * 5;    // which 4-channel chunk of the 20 channels
    if (p >= n) return;

    float px = __ldg(x + 3 * p + 0);
    float py = __ldg(x + 3 * p + 1);
    float pz = __ldg(x + 3 * p + 2);

    // (x - lo)/len * V  ==  (x+1)*64  (exact in fp32)
    float fx = (px + 1.0f) * 64.0f;
    float fy = (py + 1.0f) * 64.0f;
    float fz = (pz + 1.0f) * 64.0f;

    float gx = floorf(fx), gy = floorf(fy), gz = floorf(fz);
    float wx1 = fx - gx, wy1 = fy - gy, wz1 = fz - gz;
    float wx0 = 1.0f - wx1, wy0 = 1.0f - wy1, wz0 = 1.0f - wz1;

    int ix = (int)gx, iy = (int)gy, iz = (int)gz;
    int base = ix + (iy << 7) + (iz << 14);

    int f0 = base;
    int f1 = base + 1;
    int f2 = base + VDIM;
    int f3 = base + VDIM + 1;
    int f4 = base + VDIM * VDIM;
    int f5 = f4 + 1;
    int f6 = f4 + VDIM;
    int f7 = f6 + 1;

    // JAX gather clamps out-of-bounds flat indices (gp+1 can reach 128)
    const int last = NUM_EMB - 1;
    f0 = min(f0, last); f1 = min(f1, last); f2 = min(f2, last); f3 = min(f3, last);
    f4 = min(f4, last); f5 = min(f5, last); f6 = min(f6, last); f7 = min(f7, last);

    const __half* gH = d_gridH;
    int co = c * 4;   // channel offset within a 20-ch row (8B-aligned accesses)

    unsigned long long q0 = __ldg((const unsigned long long*)(gH + f0 * NCH + co));
    unsigned long long q1 = __ldg((const unsigned long long*)(gH + f1 * NCH + co));
    unsigned long long q2 = __ldg((const unsigned long long*)(gH + f2 * NCH + co));
    unsigned long long q3 = __ldg((const unsigned long long*)(gH + f3 * NCH + co));
    unsigned long long q4 = __ldg((const unsigned long long*)(gH + f4 * NCH + co));
    unsigned long long q5 = __ldg((const unsigned long long*)(gH + f5 * NCH + co));
    unsigned long long q6 = __ldg((const unsigned long long*)(gH + f6 * NCH + co));
    unsigned long long q7 = __ldg((const unsigned long long*)(gH + f7 * NCH + co));

    float w0 = wx0 * wy0 * wz0;
    float w1 = wx1 * wy0 * wz0;
    float w2 = wx0 * wy1 * wz0;
    float w3 = wx1 * wy1 * wz0;
    float w4 = wx0 * wy0 * wz1;
    float w5 = wx1 * wy0 * wz1;
    float w6 = wx0 * wy1 * wz1;
    float w7 = wx1 * wy1 * wz1;

    float4 r = make_float4(0.f, 0.f, 0.f, 0.f);
    acc4(r, w0, q0); acc4(r, w1, q1); acc4(r, w2, q2); acc4(r, w3, q3);
    acc4(r, w4, q4); acc4(r, w5, q5); acc4(r, w6, q6); acc4(r, w7, q7);

    stg_out((float4*)out + p * 5 + c, r);
}

extern "C" void kernel_launch(void* const* d_in, const int* in_sizes, int n_in,
                              void* d_out, int out_size) {
    const float* x    = (const float*)d_in[0];   // [n, 3] float32
    const float* grid = (const float*)d_in[1];   // [NUM_EMB, 20] float32
    float* out = (float*)d_out;                  // [n, 20] float32

    int n = in_sizes[0] / 3;

    long long cthreads = (TOTAL_F + 7) / 8;
    int cblocks = (int)((cthreads + 255) / 256);
    convert_kernel<<<cblocks, 256>>>(grid);

    warm_kernel<<<1184, 256>>>();   // 148 SMs * 8 blocks, grid-stride over 84 MB

    long long total_threads = (long long)n * 5;
    int blocks = (int)((total_threads + TPB - 1) / TPB);
    dense_grid_interp_kernel<<<blocks, TPB>>>(x, out, n);
}